// round 8
// baseline (speedup 1.0000x reference)
#include <cuda_runtime.h>
#include <cuda_bf16.h>

// GLoCELayerOutProp: B=4, T=1024, D=2048, N=8, S=8, H=8, ETA=1.
//
// R6 base (bf16 tensor-core selector GEMM Y = X @ [W|mu], exact score
// reformulation, R4-style phase 2) with:
//  R7a: single fused prologue kernel (grid 8 = concepts): packs W+mu rows to
//       bf16 AND computes muW[n,s], ||mu_n||^2 fp32 via block reduce.
//  R7b: phase 2 vectorized to 4 dims/thread: float4 x/debias/bias/out,
//       contiguous float4 upd/dgn rows (fewer LDG/STG, wider wavefronts).

#define DD    2048
#define NCON  8
#define SR    8
#define HR    8
#define TBT   16            // tokens per block
#define NT    256
#define NWARP 8
#define NCOLS 72            // 64 W cols + 8 mu cols
#define YP    80            // padded col stride
#define XBP   (DD + 8)      // bf16 x-tile row pitch

typedef unsigned int u32;

__device__ __nv_bfloat16 g_Wb[NCOLS * DD];   // [col][k]
__device__ float g_muW[64];                  // [n*8+s]
__device__ float g_mun2[NCON];

__device__ __forceinline__ float warp_sum(float v) {
    #pragma unroll
    for (int o = 16; o > 0; o >>= 1) v += __shfl_xor_sync(0xffffffffu, v, o);
    return v;
}

// ---- fused prologue: grid 8 (one block per concept) ----
__global__ void __launch_bounds__(256)
k_prep(const float* __restrict__ Wsel, const float* __restrict__ mu) {
    __shared__ float red[8][SR];
    __shared__ float redm[8];
    const int n = blockIdx.x;
    const int tid = threadIdx.x;
    const int warp = tid >> 5;
    const int lane = tid & 31;

    const float* Wn  = Wsel + (long)n * DD * SR;
    const float* mun = mu + n * DD;

    float acc[SR];
    #pragma unroll
    for (int s = 0; s < SR; s++) acc[s] = 0.f;
    float m2 = 0.f;

    #pragma unroll 2
    for (int it = 0; it < DD / 256; it++) {
        const int d = tid + 256 * it;
        const float mv = __ldg(mun + d);
        g_Wb[(64 + n) * DD + d] = __float2bfloat16_rn(mv);
        m2 = fmaf(mv, mv, m2);
        const float4 wa = __ldg(reinterpret_cast<const float4*>(Wn + (long)d * SR));
        const float4 wb = __ldg(reinterpret_cast<const float4*>(Wn + (long)d * SR + 4));
        g_Wb[(n * 8 + 0) * DD + d] = __float2bfloat16_rn(wa.x);
        g_Wb[(n * 8 + 1) * DD + d] = __float2bfloat16_rn(wa.y);
        g_Wb[(n * 8 + 2) * DD + d] = __float2bfloat16_rn(wa.z);
        g_Wb[(n * 8 + 3) * DD + d] = __float2bfloat16_rn(wa.w);
        g_Wb[(n * 8 + 4) * DD + d] = __float2bfloat16_rn(wb.x);
        g_Wb[(n * 8 + 5) * DD + d] = __float2bfloat16_rn(wb.y);
        g_Wb[(n * 8 + 6) * DD + d] = __float2bfloat16_rn(wb.z);
        g_Wb[(n * 8 + 7) * DD + d] = __float2bfloat16_rn(wb.w);
        acc[0] = fmaf(mv, wa.x, acc[0]);
        acc[1] = fmaf(mv, wa.y, acc[1]);
        acc[2] = fmaf(mv, wa.z, acc[2]);
        acc[3] = fmaf(mv, wa.w, acc[3]);
        acc[4] = fmaf(mv, wb.x, acc[4]);
        acc[5] = fmaf(mv, wb.y, acc[5]);
        acc[6] = fmaf(mv, wb.z, acc[6]);
        acc[7] = fmaf(mv, wb.w, acc[7]);
    }
    #pragma unroll
    for (int s = 0; s < SR; s++) {
        const float v = warp_sum(acc[s]);
        if (lane == 0) red[warp][s] = v;
    }
    m2 = warp_sum(m2);
    if (lane == 0) redm[warp] = m2;
    __syncthreads();
    if (tid < SR) {
        float s = 0.f;
        #pragma unroll
        for (int w = 0; w < 8; w++) s += red[w][tid];
        g_muW[n * 8 + tid] = s;
    }
    if (tid == 0) {
        float s = 0.f;
        #pragma unroll
        for (int w = 0; w < 8; w++) s += redm[w];
        g_mun2[n] = s;
    }
}

// ---- main ----
__global__ void __launch_bounds__(NT, 2)
gloce_main(const float* __restrict__ x,
           const float* __restrict__ center,
           const float* __restrict__ slope,
           const float* __restrict__ upd,
           const float* __restrict__ dgn,
           const float* __restrict__ bias_w,
           const float* __restrict__ debias_w,
           float* __restrict__ out)
{
    extern __shared__ char dsm[];
    __nv_bfloat16* xb = reinterpret_cast<__nv_bfloat16*>(dsm);   // [TBT][XBP]
    float* ysum = reinterpret_cast<float*>(dsm);                 // aliases xb

    __shared__ float yfin[TBT][YP];
    __shared__ float nx2[TBT];
    __shared__ float gates[TBT][NCON];
    __shared__ float ssel[TBT];
    __shared__ int   csel[TBT];
    __shared__ float hpart[TBT][NWARP][HR];
    __shared__ float hf_s[TBT][HR];

    const int tid  = threadIdx.x;
    const int warp = tid >> 5;
    const int lane = tid & 31;
    const long tok0 = (long)blockIdx.x * TBT;

    // ---- stage: warp w -> tokens 2w, 2w+1 ----
    #pragma unroll
    for (int q = 0; q < 2; q++) {
        const int t = 2 * warp + q;
        const float4* xr = reinterpret_cast<const float4*>(x + (tok0 + t) * DD);
        float nrm = 0.f;
        #pragma unroll 4
        for (int i = 0; i < 16; i++) {
            const float4 v = __ldg(xr + i * 32 + lane);
            nrm = fmaf(v.x, v.x, nrm);
            nrm = fmaf(v.y, v.y, nrm);
            nrm = fmaf(v.z, v.z, nrm);
            nrm = fmaf(v.w, v.w, nrm);
            __nv_bfloat162 b0 = __float22bfloat162_rn(make_float2(v.x, v.y));
            __nv_bfloat162 b1 = __float22bfloat162_rn(make_float2(v.z, v.w));
            uint2 pk = make_uint2(*reinterpret_cast<u32*>(&b0),
                                  *reinterpret_cast<u32*>(&b1));
            *reinterpret_cast<uint2*>(&xb[t * XBP + i * 128 + lane * 4]) = pk;
        }
        nrm = warp_sum(nrm);
        if (lane == 0) nx2[t] = nrm;
    }
    __syncthreads();

    // ---- GEMM: warp w covers K range [w*256, +256), 9 n-tiles ----
    {
        float d0a[9], d1a[9], d2a[9], d3a[9];
        #pragma unroll
        for (int j = 0; j < 9; j++) { d0a[j]=0.f; d1a[j]=0.f; d2a[j]=0.f; d3a[j]=0.f; }

        const int g = lane >> 2;
        const int c4 = lane & 3;

        #pragma unroll 1
        for (int kk = 0; kk < 16; kk++) {
            const int kbase = warp * 256 + kk * 16;
            const u32 a0 = *reinterpret_cast<const u32*>(&xb[g * XBP + kbase + 2 * c4]);
            const u32 a1 = *reinterpret_cast<const u32*>(&xb[(g + 8) * XBP + kbase + 2 * c4]);
            const u32 a2 = *reinterpret_cast<const u32*>(&xb[g * XBP + kbase + 2 * c4 + 8]);
            const u32 a3 = *reinterpret_cast<const u32*>(&xb[(g + 8) * XBP + kbase + 2 * c4 + 8]);
            #pragma unroll
            for (int j = 0; j < 9; j++) {
                const int col = j * 8 + g;
                const u32* bp = reinterpret_cast<const u32*>(g_Wb + col * DD + kbase);
                const u32 b0 = __ldg(bp + c4);
                const u32 b1 = __ldg(bp + c4 + 4);
                asm volatile(
                    "mma.sync.aligned.m16n8k16.row.col.f32.bf16.bf16.f32 "
                    "{%0,%1,%2,%3}, {%4,%5,%6,%7}, {%8,%9}, {%0,%1,%2,%3};"
                    : "+f"(d0a[j]), "+f"(d1a[j]), "+f"(d2a[j]), "+f"(d3a[j])
                    : "r"(a0), "r"(a1), "r"(a2), "r"(a3), "r"(b0), "r"(b1));
            }
        }
        __syncthreads();

        float* yw = ysum + warp * TBT * YP;
        #pragma unroll
        for (int j = 0; j < 9; j++) {
            const int cc = j * 8 + 2 * c4;
            *reinterpret_cast<float2*>(&yw[g * YP + cc])       = make_float2(d0a[j], d1a[j]);
            *reinterpret_cast<float2*>(&yw[(g + 8) * YP + cc]) = make_float2(d2a[j], d3a[j]);
        }
    }
    __syncthreads();

    // ---- K-reduction ----
    #pragma unroll
    for (int i = 0; i < 5; i++) {
        const int o = tid + i * NT;
        const int t = o / YP, c = o % YP;
        float s = 0.f;
        #pragma unroll
        for (int w = 0; w < NWARP; w++) s += ysum[(w * TBT + t) * YP + c];
        yfin[t][c] = s;
    }
    __syncthreads();

    // ---- scores + gates ----
    if (tid < TBT * NCON) {
        const int t = tid >> 3, n = tid & 7;
        const float xmu = yfin[t][64 + n];
        const float denom = nx2[t] - 2.f * xmu + g_mun2[n];
        float sc = 0.f;
        #pragma unroll
        for (int s = 0; s < SR; s++) {
            const float v = yfin[t][n * 8 + s] - g_muW[n * 8 + s];
            sc = fmaf(v, v, sc);
        }
        const float z = __ldg(slope + n) * (sc / denom - __ldg(center + n));
        gates[t][n] = 1.f / (1.f + __expf(-z));
    }
    __syncthreads();

    if (tid < TBT) {
        float best = gates[tid][0];
        int bi = 0;
        #pragma unroll
        for (int n = 1; n < NCON; n++) {
            const float gv = gates[tid][n];
            if (gv > best) { best = gv; bi = n; }
        }
        ssel[tid] = best;
        csel[tid] = bi;
    }
    __syncthreads();

    // ---- phase 2: warp = 256-dim D-slice, 4 dims/thread ----
    const int d0 = warp * (DD / NWARP);

    #pragma unroll 1
    for (int g2 = 0; g2 < 4; g2++) {
        int sc4[4];
        #pragma unroll
        for (int tt = 0; tt < 4; tt++) sc4[tt] = csel[g2 * 4 + tt];

        float h[4][HR];
        #pragma unroll
        for (int tt = 0; tt < 4; tt++)
            #pragma unroll
            for (int j = 0; j < HR; j++) h[tt][j] = 0.f;

        #pragma unroll 1
        for (int c = 0; c < NCON; c++) {
            bool any = false;
            #pragma unroll
            for (int tt = 0; tt < 4; tt++) any |= (sc4[tt] == c);
            if (!any) continue;

            const float* updc = upd + (long)c * DD * HR;
            const float* dbc  = debias_w + c * DD;
            #pragma unroll 1
            for (int i = 0; i < 2; i++) {
                const int d = d0 + (i * 32 + lane) * 4;
                const float4 db4 = __ldg(reinterpret_cast<const float4*>(dbc + d));
                float4 xd[4];
                #pragma unroll
                for (int tt = 0; tt < 4; tt++) {
                    if (sc4[tt] == c) {
                        const int t = g2 * 4 + tt;
                        const float4 xv = __ldg(reinterpret_cast<const float4*>(
                                                    x + (tok0 + t) * DD + d));
                        xd[tt] = make_float4(xv.x - db4.x, xv.y - db4.y,
                                             xv.z - db4.z, xv.w - db4.w);
                    }
                }
                #pragma unroll
                for (int dp = 0; dp < 4; dp++) {
                    const float4 ua = __ldg(reinterpret_cast<const float4*>(
                                                updc + (long)(d + dp) * HR));
                    const float4 ub = __ldg(reinterpret_cast<const float4*>(
                                                updc + (long)(d + dp) * HR + 4));
                    #pragma unroll
                    for (int tt = 0; tt < 4; tt++) {
                        if (sc4[tt] == c) {
                            const float xdv = (&xd[tt].x)[dp];
                            h[tt][0] = fmaf(ua.x, xdv, h[tt][0]);
                            h[tt][1] = fmaf(ua.y, xdv, h[tt][1]);
                            h[tt][2] = fmaf(ua.z, xdv, h[tt][2]);
                            h[tt][3] = fmaf(ua.w, xdv, h[tt][3]);
                            h[tt][4] = fmaf(ub.x, xdv, h[tt][4]);
                            h[tt][5] = fmaf(ub.y, xdv, h[tt][5]);
                            h[tt][6] = fmaf(ub.z, xdv, h[tt][6]);
                            h[tt][7] = fmaf(ub.w, xdv, h[tt][7]);
                        }
                    }
                }
            }
        }
        #pragma unroll
        for (int tt = 0; tt < 4; tt++) {
            #pragma unroll
            for (int j = 0; j < HR; j++) {
                const float v = warp_sum(h[tt][j]);
                if (lane == 0) hpart[g2 * 4 + tt][warp][j] = v;
            }
        }
    }
    __syncthreads();

    if (tid < TBT * HR) {
        const int t = tid >> 3, j = tid & 7;
        float s = 0.f;
        #pragma unroll
        for (int w = 0; w < NWARP; w++) s += hpart[t][w][j];
        hf_s[t][j] = s;
    }
    __syncthreads();

    // ---- output: 4 dims/thread, float4 stores ----
    #pragma unroll 1
    for (int g2 = 0; g2 < 4; g2++) {
        int   sc4[4];
        float ss4[4];
        float hf[4][HR];
        #pragma unroll
        for (int tt = 0; tt < 4; tt++) {
            sc4[tt] = csel[g2 * 4 + tt];
            ss4[tt] = ssel[g2 * 4 + tt];
            #pragma unroll
            for (int j = 0; j < HR; j++) hf[tt][j] = hf_s[g2 * 4 + tt][j];
        }

        #pragma unroll 1
        for (int c = 0; c < NCON; c++) {
            bool any = false;
            #pragma unroll
            for (int tt = 0; tt < 4; tt++) any |= (sc4[tt] == c);
            if (!any) continue;

            const float* dgnc = dgn + (long)c * DD * HR;
            const float* bnc  = bias_w + c * DD;
            #pragma unroll 1
            for (int i = 0; i < 2; i++) {
                const int d = d0 + (i * 32 + lane) * 4;
                const float4 bv4 = __ldg(reinterpret_cast<const float4*>(bnc + d));
                float dv[4][4];           // [tt][dp]
                #pragma unroll
                for (int dp = 0; dp < 4; dp++) {
                    const float4 ga = __ldg(reinterpret_cast<const float4*>(
                                                dgnc + (long)(d + dp) * HR));
                    const float4 gb = __ldg(reinterpret_cast<const float4*>(
                                                dgnc + (long)(d + dp) * HR + 4));
                    #pragma unroll
                    for (int tt = 0; tt < 4; tt++) {
                        if (sc4[tt] == c) {
                            float v = ga.x * hf[tt][0];
                            v = fmaf(ga.y, hf[tt][1], v);
                            v = fmaf(ga.z, hf[tt][2], v);
                            v = fmaf(ga.w, hf[tt][3], v);
                            v = fmaf(gb.x, hf[tt][4], v);
                            v = fmaf(gb.y, hf[tt][5], v);
                            v = fmaf(gb.z, hf[tt][6], v);
                            v = fmaf(gb.w, hf[tt][7], v);
                            dv[tt][dp] = v;
                        }
                    }
                }
                #pragma unroll
                for (int tt = 0; tt < 4; tt++) {
                    if (sc4[tt] == c) {
                        const int t = g2 * 4 + tt;
                        const float s = ss4[tt];
                        const float oms = 1.f - s;
                        const float4 xv = __ldg(reinterpret_cast<const float4*>(
                                                    x + (tok0 + t) * DD + d));
                        float4 o;
                        o.x = oms * xv.x + s * (bv4.x + dv[tt][0]);
                        o.y = oms * xv.y + s * (bv4.y + dv[tt][1]);
                        o.z = oms * xv.z + s * (bv4.z + dv[tt][2]);
                        o.w = oms * xv.w + s * (bv4.w + dv[tt][3]);
                        *reinterpret_cast<float4*>(out + (tok0 + t) * DD + d) = o;
                    }
                }
            }
        }
    }
}

extern "C" void kernel_launch(void* const* d_in, const int* in_sizes, int n_in,
                              void* d_out, int out_size) {
    const float* x      = (const float*)d_in[0];
    const float* Wsel   = (const float*)d_in[1];
    const float* mu     = (const float*)d_in[2];
    const float* center = (const float*)d_in[3];
    const float* slope  = (const float*)d_in[4];
    const float* upd    = (const float*)d_in[5];
    const float* dgn    = (const float*)d_in[6];
    const float* bias_w = (const float*)d_in[7];
    const float* debias = (const float*)d_in[8];
    float* out = (float*)d_out;

    const int tokens = in_sizes[0] / DD;                        // 4096
    const int grid   = tokens / TBT;                            // 256

    size_t smem_tile = (size_t)TBT * XBP * sizeof(__nv_bfloat16);
    size_t smem_ysum = (size_t)NWARP * TBT * YP * sizeof(float);
    size_t smem = smem_tile > smem_ysum ? smem_tile : smem_ysum;

    k_prep<<<NCON, 256>>>(Wsel, mu);

    cudaFuncSetAttribute(gloce_main,
                         cudaFuncAttributeMaxDynamicSharedMemorySize, (int)smem);
    gloce_main<<<grid, NT, smem>>>(x, center, slope, upd, dgn, bias_w, debias, out);
}

// round 9
// speedup vs baseline: 1.3547x; 1.3547x over previous
#include <cuda_runtime.h>
#include <cuda_bf16.h>

// GLoCELayerOutProp: B=4, T=1024, D=2048, N=8, S=8, H=8, ETA=1.
//
// R8 = R6 main kernel (bf16 tensor-core selector GEMM + coalesced phase 2,
//      d = d0 + lane + 32*i addressing -> 8 sectors/request on upd/dgn)
//    + R7a fused single-launch prologue (pack W|mu to bf16 + muW/||mu||^2).
// R7b's 4-dims/thread phase 2 reverted: it made each lane own a 128B line
// (32 sectors/request) and quadrupled L1 wavefronts.

#define DD    2048
#define NCON  8
#define SR    8
#define HR    8
#define TBT   16            // tokens per block
#define NT    256
#define NWARP 8
#define NCOLS 72            // 64 W cols + 8 mu cols
#define YP    80            // padded col stride
#define XBP   (DD + 8)      // bf16 x-tile row pitch

typedef unsigned int u32;

__device__ __nv_bfloat16 g_Wb[NCOLS * DD];   // [col][k]
__device__ float g_muW[64];                  // [n*8+s]
__device__ float g_mun2[NCON];

__device__ __forceinline__ float warp_sum(float v) {
    #pragma unroll
    for (int o = 16; o > 0; o >>= 1) v += __shfl_xor_sync(0xffffffffu, v, o);
    return v;
}

// ---- fused prologue: grid 8 (one block per concept) ----
__global__ void __launch_bounds__(256)
k_prep(const float* __restrict__ Wsel, const float* __restrict__ mu) {
    __shared__ float red[8][SR];
    __shared__ float redm[8];
    const int n = blockIdx.x;
    const int tid = threadIdx.x;
    const int warp = tid >> 5;
    const int lane = tid & 31;

    const float* Wn  = Wsel + (long)n * DD * SR;
    const float* mun = mu + n * DD;

    float acc[SR];
    #pragma unroll
    for (int s = 0; s < SR; s++) acc[s] = 0.f;
    float m2 = 0.f;

    #pragma unroll 2
    for (int it = 0; it < DD / 256; it++) {
        const int d = tid + 256 * it;
        const float mv = __ldg(mun + d);
        g_Wb[(64 + n) * DD + d] = __float2bfloat16_rn(mv);
        m2 = fmaf(mv, mv, m2);
        const float4 wa = __ldg(reinterpret_cast<const float4*>(Wn + (long)d * SR));
        const float4 wb = __ldg(reinterpret_cast<const float4*>(Wn + (long)d * SR + 4));
        g_Wb[(n * 8 + 0) * DD + d] = __float2bfloat16_rn(wa.x);
        g_Wb[(n * 8 + 1) * DD + d] = __float2bfloat16_rn(wa.y);
        g_Wb[(n * 8 + 2) * DD + d] = __float2bfloat16_rn(wa.z);
        g_Wb[(n * 8 + 3) * DD + d] = __float2bfloat16_rn(wa.w);
        g_Wb[(n * 8 + 4) * DD + d] = __float2bfloat16_rn(wb.x);
        g_Wb[(n * 8 + 5) * DD + d] = __float2bfloat16_rn(wb.y);
        g_Wb[(n * 8 + 6) * DD + d] = __float2bfloat16_rn(wb.z);
        g_Wb[(n * 8 + 7) * DD + d] = __float2bfloat16_rn(wb.w);
        acc[0] = fmaf(mv, wa.x, acc[0]);
        acc[1] = fmaf(mv, wa.y, acc[1]);
        acc[2] = fmaf(mv, wa.z, acc[2]);
        acc[3] = fmaf(mv, wa.w, acc[3]);
        acc[4] = fmaf(mv, wb.x, acc[4]);
        acc[5] = fmaf(mv, wb.y, acc[5]);
        acc[6] = fmaf(mv, wb.z, acc[6]);
        acc[7] = fmaf(mv, wb.w, acc[7]);
    }
    #pragma unroll
    for (int s = 0; s < SR; s++) {
        const float v = warp_sum(acc[s]);
        if (lane == 0) red[warp][s] = v;
    }
    m2 = warp_sum(m2);
    if (lane == 0) redm[warp] = m2;
    __syncthreads();
    if (tid < SR) {
        float s = 0.f;
        #pragma unroll
        for (int w = 0; w < 8; w++) s += red[w][tid];
        g_muW[n * 8 + tid] = s;
    }
    if (tid == 0) {
        float s = 0.f;
        #pragma unroll
        for (int w = 0; w < 8; w++) s += redm[w];
        g_mun2[n] = s;
    }
}

// ---- main ----
__global__ void __launch_bounds__(NT, 2)
gloce_main(const float* __restrict__ x,
           const float* __restrict__ center,
           const float* __restrict__ slope,
           const float* __restrict__ upd,
           const float* __restrict__ dgn,
           const float* __restrict__ bias_w,
           const float* __restrict__ debias_w,
           float* __restrict__ out)
{
    extern __shared__ char dsm[];
    __nv_bfloat16* xb = reinterpret_cast<__nv_bfloat16*>(dsm);   // [TBT][XBP]
    float* ysum = reinterpret_cast<float*>(dsm);                 // aliases xb

    __shared__ float yfin[TBT][YP];
    __shared__ float nx2[TBT];
    __shared__ float gates[TBT][NCON];
    __shared__ float ssel[TBT];
    __shared__ int   csel[TBT];
    __shared__ float hpart[TBT][NWARP][HR];
    __shared__ float hf_s[TBT][HR];

    const int tid  = threadIdx.x;
    const int warp = tid >> 5;
    const int lane = tid & 31;
    const long tok0 = (long)blockIdx.x * TBT;

    // ---- stage: warp w -> tokens 2w, 2w+1: fp32 -> bf16 smem, ||x||^2 ----
    #pragma unroll
    for (int q = 0; q < 2; q++) {
        const int t = 2 * warp + q;
        const float4* xr = reinterpret_cast<const float4*>(x + (tok0 + t) * DD);
        float nrm = 0.f;
        #pragma unroll 4
        for (int i = 0; i < 16; i++) {
            const float4 v = __ldg(xr + i * 32 + lane);
            nrm = fmaf(v.x, v.x, nrm);
            nrm = fmaf(v.y, v.y, nrm);
            nrm = fmaf(v.z, v.z, nrm);
            nrm = fmaf(v.w, v.w, nrm);
            __nv_bfloat162 b0 = __float22bfloat162_rn(make_float2(v.x, v.y));
            __nv_bfloat162 b1 = __float22bfloat162_rn(make_float2(v.z, v.w));
            uint2 pk = make_uint2(*reinterpret_cast<u32*>(&b0),
                                  *reinterpret_cast<u32*>(&b1));
            *reinterpret_cast<uint2*>(&xb[t * XBP + i * 128 + lane * 4]) = pk;
        }
        nrm = warp_sum(nrm);
        if (lane == 0) nx2[t] = nrm;
    }
    __syncthreads();

    // ---- GEMM: warp w covers K range [w*256, +256), 9 n-tiles ----
    {
        float d0a[9], d1a[9], d2a[9], d3a[9];
        #pragma unroll
        for (int j = 0; j < 9; j++) { d0a[j]=0.f; d1a[j]=0.f; d2a[j]=0.f; d3a[j]=0.f; }

        const int g = lane >> 2;
        const int c4 = lane & 3;

        #pragma unroll 1
        for (int kk = 0; kk < 16; kk++) {
            const int kbase = warp * 256 + kk * 16;
            const u32 a0 = *reinterpret_cast<const u32*>(&xb[g * XBP + kbase + 2 * c4]);
            const u32 a1 = *reinterpret_cast<const u32*>(&xb[(g + 8) * XBP + kbase + 2 * c4]);
            const u32 a2 = *reinterpret_cast<const u32*>(&xb[g * XBP + kbase + 2 * c4 + 8]);
            const u32 a3 = *reinterpret_cast<const u32*>(&xb[(g + 8) * XBP + kbase + 2 * c4 + 8]);
            #pragma unroll
            for (int j = 0; j < 9; j++) {
                const int col = j * 8 + g;
                const u32* bp = reinterpret_cast<const u32*>(g_Wb + col * DD + kbase);
                const u32 b0 = __ldg(bp + c4);
                const u32 b1 = __ldg(bp + c4 + 4);
                asm volatile(
                    "mma.sync.aligned.m16n8k16.row.col.f32.bf16.bf16.f32 "
                    "{%0,%1,%2,%3}, {%4,%5,%6,%7}, {%8,%9}, {%0,%1,%2,%3};"
                    : "+f"(d0a[j]), "+f"(d1a[j]), "+f"(d2a[j]), "+f"(d3a[j])
                    : "r"(a0), "r"(a1), "r"(a2), "r"(a3), "r"(b0), "r"(b1));
            }
        }
        __syncthreads();   // all warps done reading xb -> safe to alias as ysum

        float* yw = ysum + warp * TBT * YP;
        #pragma unroll
        for (int j = 0; j < 9; j++) {
            const int cc = j * 8 + 2 * c4;
            *reinterpret_cast<float2*>(&yw[g * YP + cc])       = make_float2(d0a[j], d1a[j]);
            *reinterpret_cast<float2*>(&yw[(g + 8) * YP + cc]) = make_float2(d2a[j], d3a[j]);
        }
    }
    __syncthreads();

    // ---- K-reduction: 16x80 outputs ----
    #pragma unroll
    for (int i = 0; i < 5; i++) {
        const int o = tid + i * NT;
        const int t = o / YP, c = o % YP;
        float s = 0.f;
        #pragma unroll
        for (int w = 0; w < NWARP; w++) s += ysum[(w * TBT + t) * YP + c];
        yfin[t][c] = s;
    }
    __syncthreads();

    // ---- scores + gates ----
    if (tid < TBT * NCON) {
        const int t = tid >> 3, n = tid & 7;
        const float xmu = yfin[t][64 + n];
        const float denom = nx2[t] - 2.f * xmu + g_mun2[n];
        float sc = 0.f;
        #pragma unroll
        for (int s = 0; s < SR; s++) {
            const float v = yfin[t][n * 8 + s] - g_muW[n * 8 + s];
            sc = fmaf(v, v, sc);
        }
        const float z = __ldg(slope + n) * (sc / denom - __ldg(center + n));
        gates[t][n] = 1.f / (1.f + __expf(-z));
    }
    __syncthreads();

    if (tid < TBT) {
        float best = gates[tid][0];
        int bi = 0;
        #pragma unroll
        for (int n = 1; n < NCON; n++) {
            const float gv = gates[tid][n];
            if (gv > best) { best = gv; bi = n; }
        }
        ssel[tid] = best;
        csel[tid] = bi;
    }
    __syncthreads();

    // ---- phase 2: warp = 256-dim D-slice, coalesced d = d0+lane+32i ----
    const int d0 = warp * (DD / NWARP);

    #pragma unroll 1
    for (int g2 = 0; g2 < 4; g2++) {
        int sc4[4];
        #pragma unroll
        for (int tt = 0; tt < 4; tt++) sc4[tt] = csel[g2 * 4 + tt];

        float h[4][HR];
        #pragma unroll
        for (int tt = 0; tt < 4; tt++)
            #pragma unroll
            for (int j = 0; j < HR; j++) h[tt][j] = 0.f;

        #pragma unroll 1
        for (int c = 0; c < NCON; c++) {
            bool any = false;
            #pragma unroll
            for (int tt = 0; tt < 4; tt++) any |= (sc4[tt] == c);
            if (!any) continue;

            const float* updc = upd + (long)c * DD * HR;
            const float* dbc  = debias_w + c * DD;
            #pragma unroll 2
            for (int i = 0; i < 8; i++) {
                const int d = d0 + lane + 32 * i;
                const float db = __ldg(dbc + d);
                const float4 ua = __ldg(reinterpret_cast<const float4*>(updc + (long)d * HR));
                const float4 ub = __ldg(reinterpret_cast<const float4*>(updc + (long)d * HR + 4));
                #pragma unroll
                for (int tt = 0; tt < 4; tt++) {
                    if (sc4[tt] == c) {
                        const int t = g2 * 4 + tt;
                        const float xd = __ldg(x + (tok0 + t) * DD + d) - db;
                        h[tt][0] = fmaf(ua.x, xd, h[tt][0]);
                        h[tt][1] = fmaf(ua.y, xd, h[tt][1]);
                        h[tt][2] = fmaf(ua.z, xd, h[tt][2]);
                        h[tt][3] = fmaf(ua.w, xd, h[tt][3]);
                        h[tt][4] = fmaf(ub.x, xd, h[tt][4]);
                        h[tt][5] = fmaf(ub.y, xd, h[tt][5]);
                        h[tt][6] = fmaf(ub.z, xd, h[tt][6]);
                        h[tt][7] = fmaf(ub.w, xd, h[tt][7]);
                    }
                }
            }
        }
        #pragma unroll
        for (int tt = 0; tt < 4; tt++) {
            #pragma unroll
            for (int j = 0; j < HR; j++) {
                const float v = warp_sum(h[tt][j]);
                if (lane == 0) hpart[g2 * 4 + tt][warp][j] = v;
            }
        }
    }
    __syncthreads();

    if (tid < TBT * HR) {
        const int t = tid >> 3, j = tid & 7;
        float s = 0.f;
        #pragma unroll
        for (int w = 0; w < NWARP; w++) s += hpart[t][w][j];
        hf_s[t][j] = s;
    }
    __syncthreads();

    // ---- output ----
    #pragma unroll 1
    for (int g2 = 0; g2 < 4; g2++) {
        int   sc4[4];
        float ss4[4];
        float hf[4][HR];
        #pragma unroll
        for (int tt = 0; tt < 4; tt++) {
            sc4[tt] = csel[g2 * 4 + tt];
            ss4[tt] = ssel[g2 * 4 + tt];
            #pragma unroll
            for (int j = 0; j < HR; j++) hf[tt][j] = hf_s[g2 * 4 + tt][j];
        }

        #pragma unroll 1
        for (int c = 0; c < NCON; c++) {
            bool any = false;
            #pragma unroll
            for (int tt = 0; tt < 4; tt++) any |= (sc4[tt] == c);
            if (!any) continue;

            const float* dgnc = dgn + (long)c * DD * HR;
            const float* bnc  = bias_w + c * DD;
            #pragma unroll 2
            for (int i = 0; i < 8; i++) {
                const int d = d0 + lane + 32 * i;
                const float bv = __ldg(bnc + d);
                const float4 ga = __ldg(reinterpret_cast<const float4*>(dgnc + (long)d * HR));
                const float4 gb = __ldg(reinterpret_cast<const float4*>(dgnc + (long)d * HR + 4));
                #pragma unroll
                for (int tt = 0; tt < 4; tt++) {
                    if (sc4[tt] == c) {
                        const int t = g2 * 4 + tt;
                        float dv = ga.x * hf[tt][0];
                        dv = fmaf(ga.y, hf[tt][1], dv);
                        dv = fmaf(ga.z, hf[tt][2], dv);
                        dv = fmaf(ga.w, hf[tt][3], dv);
                        dv = fmaf(gb.x, hf[tt][4], dv);
                        dv = fmaf(gb.y, hf[tt][5], dv);
                        dv = fmaf(gb.z, hf[tt][6], dv);
                        dv = fmaf(gb.w, hf[tt][7], dv);
                        const float s = ss4[tt];
                        const float xv = __ldg(x + (tok0 + t) * DD + d);
                        out[(tok0 + t) * DD + d] = (1.f - s) * xv + s * (bv + dv);
                    }
                }
            }
        }
    }
}

extern "C" void kernel_launch(void* const* d_in, const int* in_sizes, int n_in,
                              void* d_out, int out_size) {
    const float* x      = (const float*)d_in[0];
    const float* Wsel   = (const float*)d_in[1];
    const float* mu     = (const float*)d_in[2];
    const float* center = (const float*)d_in[3];
    const float* slope  = (const float*)d_in[4];
    const float* upd    = (const float*)d_in[5];
    const float* dgn    = (const float*)d_in[6];
    const float* bias_w = (const float*)d_in[7];
    const float* debias = (const float*)d_in[8];
    float* out = (float*)d_out;

    const int tokens = in_sizes[0] / DD;                        // 4096
    const int grid   = tokens / TBT;                            // 256

    size_t smem_tile = (size_t)TBT * XBP * sizeof(__nv_bfloat16);
    size_t smem_ysum = (size_t)NWARP * TBT * YP * sizeof(float);
    size_t smem = smem_tile > smem_ysum ? smem_tile : smem_ysum;

    k_prep<<<NCON, 256>>>(Wsel, mu);

    cudaFuncSetAttribute(gloce_main,
                         cudaFuncAttributeMaxDynamicSharedMemorySize, (int)smem);
    gloce_main<<<grid, NT, smem>>>(x, center, slope, upd, dgn, bias_w, debias, out);
}